// round 16
// baseline (speedup 1.0000x reference)
#include <cuda_runtime.h>
#include <cuda_bf16.h>

// out[b, n] = ACT[act_codes[n]](x[b, n]),  x: [B, N] fp32, N = C*H*W
// Codes: 0=relu, 1=sigmoid, 2=tanh, 3=elu(a=1), 4=leaky_relu(0.01), 5=gelu(tanh)
//
// R16: R12 memory config (float4 LDG.128 default policy, STG.128 evict-first
// via __stcs, ROWS=16, batch-4 loads) + R6 lean packed-f32x2 math:
//   r = a1*x + a2*|x| + aen*e^{min(x,0)} + ac + (m*x+b)*tanh(x*(cl+cq*x^2))
// which removes one add, one fma, and both scalar fmins vs R12's act2.

typedef unsigned long long u64;

__device__ __forceinline__ float f_tanh(float x) {
    float r; asm("tanh.approx.f32 %0, %1;" : "=f"(r) : "f"(x)); return r;
}
__device__ __forceinline__ float f_ex2(float x) {
    float r; asm("ex2.approx.f32 %0, %1;" : "=f"(r) : "f"(x)); return r;
}

__device__ __forceinline__ u64 pk(float lo, float hi) {
    u64 r; asm("mov.b64 %0, {%1, %2};" : "=l"(r) : "f"(lo), "f"(hi)); return r;
}
__device__ __forceinline__ float2 upk(u64 v) {
    float2 f; asm("mov.b64 {%0, %1}, %2;" : "=f"(f.x), "=f"(f.y) : "l"(v)); return f;
}
__device__ __forceinline__ u64 f2fma(u64 a, u64 b, u64 c) {
    u64 d; asm("fma.rn.f32x2 %0, %1, %2, %3;" : "=l"(d) : "l"(a), "l"(b), "l"(c)); return d;
}
__device__ __forceinline__ u64 f2mul(u64 a, u64 b) {
    u64 d; asm("mul.rn.f32x2 %0, %1, %2;" : "=l"(d) : "l"(a), "l"(b)); return d;
}
__device__ __forceinline__ u64 f2sub(u64 a, u64 b) {
    u64 d; asm("sub.rn.f32x2 %0, %1, %2;" : "=l"(d) : "l"(a), "l"(b)); return d;
}

#define ROWS 16

// ---- per-code scalar coefficients (lean basis) -------------------------
// r = a1*x + a2*|x| + aen*e^{min(x,0)} + ac + (m*x+b)*tanh(x*(cl+cq*x^2))
struct CoefS { float a1, a2, aen, ac, m, b, cl, cq; };

__device__ __forceinline__ CoefS make_coef(int c) {
    CoefS k;
    k.a1  = (c == 0 || c == 3 || c == 5) ? 0.5f : ((c == 4) ? 0.505f : 0.0f);
    k.a2  = (c == 0 || c == 3) ? 0.5f : ((c == 4) ? 0.495f : 0.0f);
    k.aen = (c == 3) ? 1.0f : 0.0f;
    k.ac  = (c == 1) ? 0.5f : ((c == 3) ? -1.0f : 0.0f);
    k.m   = (c == 5) ? 0.5f : 0.0f;
    k.b   = (c == 2) ? 1.0f : ((c == 1) ? 0.5f : 0.0f);
    k.cl  = (c == 2) ? 1.0f : ((c == 1) ? 0.5f : ((c == 5) ? 0.7978845608028654f : 0.0f));
    k.cq  = (c == 5) ? 0.0356774081363001f : 0.0f;
    return k;
}

// packed (two columns) coefficients: 8 u64 = 16 regs
struct CoefP { u64 a1, a2, aen, ac, m, b, cl, cq; };

__device__ __forceinline__ CoefP pack_coef(const CoefS& a, const CoefS& b2) {
    CoefP p;
    p.a1  = pk(a.a1,  b2.a1);   p.a2  = pk(a.a2,  b2.a2);
    p.aen = pk(a.aen, b2.aen);  p.ac  = pk(a.ac,  b2.ac);
    p.m   = pk(a.m,   b2.m);    p.b   = pk(a.b,   b2.b);
    p.cl  = pk(a.cl,  b2.cl);   p.cq  = pk(a.cq,  b2.cq);
    return p;
}

__device__ __forceinline__ u64 act2(u64 xv, const CoefP& k) {
    const u64 ABS  = 0x7FFFFFFF7FFFFFFFULL;
    const u64 HL2E = 0x3F38AA3B3F38AA3BULL;  // (0.5*log2e, 0.5*log2e)

    u64 ax  = xv & ABS;                 // |x|
    u64 xn  = f2sub(xv, ax);            // 2*min(x,0)
    u64 em  = f2mul(xn, HL2E);          // min(x,0)*log2e
    u64 x2  = f2mul(xv, xv);
    u64 q   = f2fma(k.cq, x2, k.cl);
    u64 ta  = f2mul(q, xv);             // tanh argument

    float2 taf = upk(ta);
    float2 emf = upk(em);
    float th0 = f_tanh(taf.x);
    float th1 = f_tanh(taf.y);
    float en0 = f_ex2(emf.x);           // e^{min(x,0)} in (0,1], ==1 at x>=0
    float en1 = f_ex2(emf.y);
    u64 th = pk(th0, th1);
    u64 en = pk(en0, en1);

    u64 t = f2fma(k.m, xv, k.b);
    u64 r = f2fma(k.a1, xv, k.ac);
    r = f2fma(k.a2,  ax, r);
    r = f2fma(k.aen, en, r);
    r = f2fma(t,     th, r);
    return r;
}

// One thread = one float4 column group (2 packed pairs), ROWS rows.
__global__ void __launch_bounds__(256) act_select_p2(
    const ulonglong2* __restrict__ x,
    const int4*  __restrict__ codes,
    ulonglong2* __restrict__ out,
    int N4) {
    int n4 = blockIdx.x * blockDim.x + threadIdx.x;
    if (n4 >= N4) return;

    int4 c = codes[n4];
    CoefP kA = pack_coef(make_coef(c.x), make_coef(c.y));
    CoefP kB = pack_coef(make_coef(c.z), make_coef(c.w));

    size_t base = (size_t)blockIdx.y * ROWS * N4 + n4;

#pragma unroll
    for (int rr = 0; rr < ROWS; rr += 4) {
        ulonglong2 v[4];
#pragma unroll
        for (int i = 0; i < 4; i++)
            v[i] = x[base + (size_t)(rr + i) * N4];
#pragma unroll
        for (int i = 0; i < 4; i++) {
            ulonglong2 o;
            o.x = act2(v[i].x, kA);
            o.y = act2(v[i].y, kB);
            __stcs(&out[base + (size_t)(rr + i) * N4], o);  // evict-first store
        }
    }
}

// ---- generic scalar fallback -------------------------------------------
__device__ __forceinline__ float act1(float x, const CoefS& k) {
    float ax  = fabsf(x);
    float ta  = x * fmaf(k.cq, x * x, k.cl);
    float en  = f_ex2((x - ax) * 0.7213475204444817f);
    float th  = f_tanh(ta);
    float t   = fmaf(k.m, x, k.b);
    float r   = fmaf(k.a1, x, k.ac);
    r = fmaf(k.a2,  ax, r);
    r = fmaf(k.aen, en, r);
    r = fmaf(t,     th, r);
    return r;
}

__global__ void act_select_scalar(const float* __restrict__ x,
                                  const int*  __restrict__ codes,
                                  float* __restrict__ out,
                                  int N) {
    int n = blockIdx.x * blockDim.x + threadIdx.x;
    if (n >= N) return;
    CoefS k = make_coef(codes[n]);
    size_t idx = (size_t)blockIdx.y * N + n;
    out[idx] = act1(x[idx], k);
}

extern "C" void kernel_launch(void* const* d_in, const int* in_sizes, int n_in,
                              void* d_out, int out_size) {
    const float* x     = (const float*)d_in[0];
    const int*   codes = (const int*)d_in[1];
    float*       out   = (float*)d_out;

    int N = in_sizes[1];            // C*H*W
    int B = out_size / N;

    if ((N & 3) == 0 && (B % ROWS) == 0) {
        int N4 = N >> 2;
        dim3 block(256);
        dim3 grid((N4 + 255) / 256, B / ROWS);
        act_select_p2<<<grid, block>>>((const ulonglong2*)x, (const int4*)codes,
                                       (ulonglong2*)out, N4);
    } else {
        dim3 block(256);
        dim3 grid((N + 255) / 256, B);
        act_select_scalar<<<grid, block>>>(x, codes, out, N);
    }
}

// round 17
// speedup vs baseline: 1.1615x; 1.1615x over previous
#include <cuda_runtime.h>
#include <cuda_bf16.h>

// out[b, n] = ACT[act_codes[n]](x[b, n]),  x: [B, N] fp32, N = C*H*W
// Codes: 0=relu, 1=sigmoid, 2=tanh, 3=elu(a=1), 4=leaky_relu(0.01), 5=gelu(tanh)
//
// R17: R12 (best measured: 36.1us kernel) with a software-pipelined prologue —
// first x batch issued BEFORE the codes load/decode so the code fetch + ~60-op
// predicate decode overlaps the first DRAM miss instead of preceding it.
// Steady state identical to R12: float4 loads (default policy), __stcs stores,
// ROWS=16, batch-4, R4 shallow-dependency packed-f32x2 math.

typedef unsigned long long u64;

__device__ __forceinline__ float f_tanh(float x) {
    float r; asm("tanh.approx.f32 %0, %1;" : "=f"(r) : "f"(x)); return r;
}
__device__ __forceinline__ float f_ex2(float x) {
    float r; asm("ex2.approx.f32 %0, %1;" : "=f"(r) : "f"(x)); return r;
}

__device__ __forceinline__ u64 pk(float lo, float hi) {
    u64 r; asm("mov.b64 %0, {%1, %2};" : "=l"(r) : "f"(lo), "f"(hi)); return r;
}
__device__ __forceinline__ float2 upk(u64 v) {
    float2 f; asm("mov.b64 {%0, %1}, %2;" : "=f"(f.x), "=f"(f.y) : "l"(v)); return f;
}
__device__ __forceinline__ u64 f2fma(u64 a, u64 b, u64 c) {
    u64 d; asm("fma.rn.f32x2 %0, %1, %2, %3;" : "=l"(d) : "l"(a), "l"(b), "l"(c)); return d;
}
__device__ __forceinline__ u64 f2mul(u64 a, u64 b) {
    u64 d; asm("mul.rn.f32x2 %0, %1, %2;" : "=l"(d) : "l"(a), "l"(b)); return d;
}
__device__ __forceinline__ u64 f2add(u64 a, u64 b) {
    u64 d; asm("add.rn.f32x2 %0, %1, %2;" : "=l"(d) : "l"(a), "l"(b)); return d;
}

#define ROWS 16

// ---- per-code scalar coefficients --------------------------------------
struct CoefS { float axp, axn, aen, ac, m, b, cl, cq; };

__device__ __forceinline__ CoefS make_coef(int c) {
    CoefS k;
    k.axp = (c == 0 || c == 3 || c == 4) ? 0.5f : ((c == 5) ? 0.25f : 0.0f);
    k.axn = (c == 4) ? 0.005f : ((c == 5) ? 0.25f : 0.0f);
    k.aen = (c == 3) ? 1.0f : 0.0f;
    k.ac  = (c == 1) ? 0.5f : ((c == 3) ? -1.0f : 0.0f);
    k.m   = (c == 5) ? 0.5f : 0.0f;
    k.b   = (c == 2) ? 1.0f : ((c == 1) ? 0.5f : 0.0f);
    k.cl  = (c == 2) ? 1.0f : ((c == 1) ? 0.5f : ((c == 5) ? 0.7978845608028654f : 0.0f));
    k.cq  = (c == 5) ? 0.0356774081363001f : 0.0f;
    return k;
}

// packed (two columns) coefficients: 8 u64 = 16 regs
struct CoefP { u64 axp, axn, aen, ac, m, b, cl, cq; };

__device__ __forceinline__ CoefP pack_coef(const CoefS& a, const CoefS& b2) {
    CoefP p;
    p.axp = pk(a.axp, b2.axp);  p.axn = pk(a.axn, b2.axn);
    p.aen = pk(a.aen, b2.aen);  p.ac  = pk(a.ac,  b2.ac);
    p.m   = pk(a.m,   b2.m);    p.b   = pk(a.b,   b2.b);
    p.cl  = pk(a.cl,  b2.cl);   p.cq  = pk(a.cq,  b2.cq);
    return p;
}

__device__ __forceinline__ u64 act2(u64 xv, const CoefP& k) {
    const u64 ABS  = 0x7FFFFFFF7FFFFFFFULL;
    const u64 NEG1 = 0xBF800000BF800000ULL;  // (-1, -1)
    const u64 L2E  = 0x3FB8AA3B3FB8AA3BULL;  // (log2e, log2e)

    u64 ax  = xv & ABS;
    u64 xpb = f2add(xv, ax);            // x + |x|
    u64 xnb = f2fma(ax, NEG1, xv);      // x - |x|
    u64 x2  = f2mul(xv, xv);
    u64 q   = f2fma(k.cq, x2, k.cl);
    u64 ta  = f2mul(q, xv);             // tanh argument
    u64 em  = f2mul(xv, L2E);           // x * log2(e)  (depth-1 from load)

    float2 taf = upk(ta);
    float2 emf = upk(em);
    float th0 = f_tanh(taf.x);
    float th1 = f_tanh(taf.y);
    float en0 = fminf(f_ex2(emf.x), 1.0f);
    float en1 = fminf(f_ex2(emf.y), 1.0f);
    u64 th = pk(th0, th1);
    u64 en = pk(en0, en1);

    u64 t = f2fma(k.m, xv, k.b);
    u64 r = f2fma(k.axp, xpb, k.ac);
    r = f2fma(k.axn, xnb, r);
    r = f2fma(k.aen, en,  r);
    r = f2fma(t,     th,  r);
    return r;
}

// One thread = one float4 column group (2 packed pairs), ROWS rows.
// Prologue pipelined: first x batch issued before codes load + decode.
__global__ void __launch_bounds__(256) act_select_p2(
    const ulonglong2* __restrict__ x,
    const int4*  __restrict__ codes,
    ulonglong2* __restrict__ out,
    int N4) {
    int n4 = blockIdx.x * blockDim.x + threadIdx.x;
    if (n4 >= N4) return;

    size_t base = (size_t)blockIdx.y * ROWS * N4 + n4;

    // Batch 0 x loads first — overlap codes fetch + decode with their latency.
    ulonglong2 v0[4];
#pragma unroll
    for (int i = 0; i < 4; i++)
        v0[i] = x[base + (size_t)i * N4];

    int4 c = codes[n4];
    CoefP kA = pack_coef(make_coef(c.x), make_coef(c.y));
    CoefP kB = pack_coef(make_coef(c.z), make_coef(c.w));

#pragma unroll
    for (int i = 0; i < 4; i++) {
        ulonglong2 o;
        o.x = act2(v0[i].x, kA);
        o.y = act2(v0[i].y, kB);
        __stcs(&out[base + (size_t)i * N4], o);
    }

#pragma unroll
    for (int rr = 4; rr < ROWS; rr += 4) {
        ulonglong2 v[4];
#pragma unroll
        for (int i = 0; i < 4; i++)
            v[i] = x[base + (size_t)(rr + i) * N4];
#pragma unroll
        for (int i = 0; i < 4; i++) {
            ulonglong2 o;
            o.x = act2(v[i].x, kA);
            o.y = act2(v[i].y, kB);
            __stcs(&out[base + (size_t)(rr + i) * N4], o);
        }
    }
}

// ---- generic scalar fallback -------------------------------------------
__device__ __forceinline__ float act1(float x, const CoefS& k) {
    float ax  = fabsf(x);
    float xpb = x + ax;
    float xnb = x - ax;
    float ta  = x * fmaf(k.cq, x * x, k.cl);
    float en  = fminf(f_ex2(x * 1.4426950408889634f), 1.0f);
    float th  = f_tanh(ta);
    float t   = fmaf(k.m, x, k.b);
    float r   = fmaf(k.axp, xpb, k.ac);
    r = fmaf(k.axn, xnb, r);
    r = fmaf(k.aen, en,  r);
    r = fmaf(t,     th,  r);
    return r;
}

__global__ void act_select_scalar(const float* __restrict__ x,
                                  const int*  __restrict__ codes,
                                  float* __restrict__ out,
                                  int N) {
    int n = blockIdx.x * blockDim.x + threadIdx.x;
    if (n >= N) return;
    CoefS k = make_coef(codes[n]);
    size_t idx = (size_t)blockIdx.y * N + n;
    out[idx] = act1(x[idx], k);
}

extern "C" void kernel_launch(void* const* d_in, const int* in_sizes, int n_in,
                              void* d_out, int out_size) {
    const float* x     = (const float*)d_in[0];
    const int*   codes = (const int*)d_in[1];
    float*       out   = (float*)d_out;

    int N = in_sizes[1];            // C*H*W
    int B = out_size / N;

    if ((N & 3) == 0 && (B % ROWS) == 0) {
        int N4 = N >> 2;
        dim3 block(256);
        dim3 grid((N4 + 255) / 256, B / ROWS);
        act_select_p2<<<grid, block>>>((const ulonglong2*)x, (const int4*)codes,
                                       (ulonglong2*)out, N4);
    } else {
        dim3 block(256);
        dim3 grid((N + 255) / 256, B);
        act_select_scalar<<<grid, block>>>(x, codes, out, N);
    }
}